// round 2
// baseline (speedup 1.0000x reference)
#include <cuda_runtime.h>
#include <math.h>

// Problem dims (fixed by reference setup_inputs)
#define BATCH 8
#define SQ    2048
#define SKV   2048
#define HID   1024

// Scratch (allocation-free rule: __device__ globals)
__device__ float g_Q[(size_t)BATCH * SQ  * HID];   // 64 MB
__device__ float g_K[(size_t)BATCH * SKV * HID];   // 64 MB
__device__ float g_V[(size_t)BATCH * SKV * HID];   // 64 MB
__device__ float g_S[(size_t)BATCH * SQ  * SKV];   // 128 MB

// ---------------------------------------------------------------------------
// fp32 SIMT GEMM, double-buffered smem with register staging.
//   C[M,N] = A[M,K] * B (+epilogue)
//   BT=false: B is [K,N] row-major (NN)
//   BT=true : B is [N,K] row-major (NT: C = A * B^T)
// EPI: 0 = plain store
//      1 = + bias[n]
//      2 = scores: c*scale + (1-mask[bz*N+n])*(-10000)
// Tiles: BM=BN=128, BK=16, 256 threads, 8x8 per thread.
// Requires M%128==0, N%128==0, K%16==0 (true for all shapes here).
// ---------------------------------------------------------------------------
template<bool BT, int EPI>
__global__ __launch_bounds__(256, 2)
void gemm_kern(const float* __restrict__ A, const float* __restrict__ Bm,
               const float* __restrict__ E, float* __restrict__ C,
               int M, int N, int K,
               size_t sA, size_t sB, size_t sC, float scale)
{
    const int bz = blockIdx.z;
    const float* Ab = A  + (size_t)bz * sA;
    const float* Bb = Bm + (size_t)bz * sB;
    float*       Cb = C  + (size_t)bz * sC;

    const int bm = blockIdx.y * 128;
    const int bn = blockIdx.x * 128;
    const int tid = threadIdx.x;
    const int tx = tid & 15;        // n direction
    const int ty = tid >> 4;        // m direction

    __shared__ float As[2][16][128];
    __shared__ float Bs[2][16][128];

    // Each thread stages 2 float4 of A and 2 float4 of B per K-step.
    // A slot s (0..511): row = s>>2 (m within tile), kq = s&3 (float4 along k)
    const int aslot0 = tid, aslot1 = tid + 256;
    const int ar0 = aslot0 >> 2, ak0 = aslot0 & 3;
    const int ar1 = aslot1 >> 2, ak1 = aslot1 & 3;

    float4 fa0, fa1, fb0, fb1;

    // fetch helpers (inlined via lambdas)
    auto fetchA = [&](int k0) {
        fa0 = *reinterpret_cast<const float4*>(Ab + (size_t)(bm + ar0) * K + k0 + ak0 * 4);
        fa1 = *reinterpret_cast<const float4*>(Ab + (size_t)(bm + ar1) * K + k0 + ak1 * 4);
    };
    auto storeA = [&](int buf) {
        As[buf][ak0 * 4 + 0][ar0] = fa0.x;
        As[buf][ak0 * 4 + 1][ar0] = fa0.y;
        As[buf][ak0 * 4 + 2][ar0] = fa0.z;
        As[buf][ak0 * 4 + 3][ar0] = fa0.w;
        As[buf][ak1 * 4 + 0][ar1] = fa1.x;
        As[buf][ak1 * 4 + 1][ar1] = fa1.y;
        As[buf][ak1 * 4 + 2][ar1] = fa1.z;
        As[buf][ak1 * 4 + 3][ar1] = fa1.w;
    };
    auto fetchB = [&](int k0) {
        if (BT) {
            // B[N][K]: same slot scheme as A (row = n within tile)
            fb0 = *reinterpret_cast<const float4*>(Bb + (size_t)(bn + ar0) * K + k0 + ak0 * 4);
            fb1 = *reinterpret_cast<const float4*>(Bb + (size_t)(bn + ar1) * K + k0 + ak1 * 4);
        } else {
            // B[K][N]: slot s: krow = s>>5 (0..15), cq = s&31 (float4 along n)
            const int kr0 = aslot0 >> 5, cq0 = aslot0 & 31;
            const int kr1 = aslot1 >> 5, cq1 = aslot1 & 31;
            fb0 = *reinterpret_cast<const float4*>(Bb + (size_t)(k0 + kr0) * N + bn + cq0 * 4);
            fb1 = *reinterpret_cast<const float4*>(Bb + (size_t)(k0 + kr1) * N + bn + cq1 * 4);
        }
    };
    auto storeB = [&](int buf) {
        if (BT) {
            Bs[buf][ak0 * 4 + 0][ar0] = fb0.x;
            Bs[buf][ak0 * 4 + 1][ar0] = fb0.y;
            Bs[buf][ak0 * 4 + 2][ar0] = fb0.z;
            Bs[buf][ak0 * 4 + 3][ar0] = fb0.w;
            Bs[buf][ak1 * 4 + 0][ar1] = fb1.x;
            Bs[buf][ak1 * 4 + 1][ar1] = fb1.y;
            Bs[buf][ak1 * 4 + 2][ar1] = fb1.z;
            Bs[buf][ak1 * 4 + 3][ar1] = fb1.w;
        } else {
            const int kr0 = aslot0 >> 5, cq0 = aslot0 & 31;
            const int kr1 = aslot1 >> 5, cq1 = aslot1 & 31;
            *reinterpret_cast<float4*>(&Bs[buf][kr0][cq0 * 4]) = fb0;
            *reinterpret_cast<float4*>(&Bs[buf][kr1][cq1 * 4]) = fb1;
        }
    };

    float acc[8][8];
#pragma unroll
    for (int i = 0; i < 8; i++)
#pragma unroll
        for (int j = 0; j < 8; j++) acc[i][j] = 0.f;

    // Prologue: tile 0 into buffer 0
    fetchA(0); fetchB(0);
    storeA(0); storeB(0);
    __syncthreads();

    int cur = 0;
    for (int k0 = 16; k0 <= K; k0 += 16) {
        const bool more = (k0 < K);
        if (more) { fetchA(k0); fetchB(k0); }   // LDGs in flight during compute

        // ---- compute on buffer `cur` ----
#pragma unroll
        for (int kk = 0; kk < 16; kk++) {
            float ra[8], rb[8];
#pragma unroll
            for (int i = 0; i < 4; i++) {
                ra[i]     = As[cur][kk][ty * 4 + i];
                ra[4 + i] = As[cur][kk][64 + ty * 4 + i];
            }
#pragma unroll
            for (int j = 0; j < 4; j++) {
                rb[j]     = Bs[cur][kk][tx * 4 + j];
                rb[4 + j] = Bs[cur][kk][64 + tx * 4 + j];
            }
#pragma unroll
            for (int i = 0; i < 8; i++)
#pragma unroll
                for (int j = 0; j < 8; j++)
                    acc[i][j] += ra[i] * rb[j];
        }

        if (more) {
            storeA(cur ^ 1); storeB(cur ^ 1);
            __syncthreads();
            cur ^= 1;
        }
    }

    // ---- epilogue + store (two float4 per m-row) ----
#pragma unroll
    for (int i = 0; i < 8; i++) {
        const int m = bm + ((i < 4) ? (ty * 4 + i) : (64 + ty * 4 + (i - 4)));
#pragma unroll
        for (int jh = 0; jh < 2; jh++) {
            const int n0 = bn + (jh ? (64 + tx * 4) : (tx * 4));
            float4 v;
            v.x = acc[i][jh * 4 + 0];
            v.y = acc[i][jh * 4 + 1];
            v.z = acc[i][jh * 4 + 2];
            v.w = acc[i][jh * 4 + 3];
            if (EPI == 1) {
                v.x += E[n0 + 0]; v.y += E[n0 + 1];
                v.z += E[n0 + 2]; v.w += E[n0 + 3];
            } else if (EPI == 2) {
                const float* mask = E + (size_t)bz * N;
                v.x = v.x * scale + (1.f - mask[n0 + 0]) * -10000.f;
                v.y = v.y * scale + (1.f - mask[n0 + 1]) * -10000.f;
                v.z = v.z * scale + (1.f - mask[n0 + 2]) * -10000.f;
                v.w = v.w * scale + (1.f - mask[n0 + 3]) * -10000.f;
            }
            *reinterpret_cast<float4*>(Cb + (size_t)m * N + n0) = v;
        }
    }
}

// ---------------------------------------------------------------------------
// Row softmax over N=2048, one block (256 threads) per row, in place.
// ---------------------------------------------------------------------------
__device__ __forceinline__ float warp_max(float v) {
#pragma unroll
    for (int o = 16; o; o >>= 1) v = fmaxf(v, __shfl_xor_sync(0xFFFFFFFFu, v, o));
    return v;
}
__device__ __forceinline__ float warp_sum(float v) {
#pragma unroll
    for (int o = 16; o; o >>= 1) v += __shfl_xor_sync(0xFFFFFFFFu, v, o);
    return v;
}

__global__ __launch_bounds__(256)
void softmax_kern(float* __restrict__ S)
{
    const size_t row = blockIdx.x;
    float* p = S + row * (size_t)SKV;
    const int tid = threadIdx.x;

    float4 v0 = *reinterpret_cast<const float4*>(p + tid * 4);
    float4 v1 = *reinterpret_cast<const float4*>(p + 1024 + tid * 4);

    float m = fmaxf(fmaxf(fmaxf(v0.x, v0.y), fmaxf(v0.z, v0.w)),
                    fmaxf(fmaxf(v1.x, v1.y), fmaxf(v1.z, v1.w)));

    __shared__ float red[8];
    float wm = warp_max(m);
    if ((tid & 31) == 0) red[tid >> 5] = wm;
    __syncthreads();
    float bm = red[0];
#pragma unroll
    for (int i = 1; i < 8; i++) bm = fmaxf(bm, red[i]);
    __syncthreads();

    v0.x = expf(v0.x - bm); v0.y = expf(v0.y - bm);
    v0.z = expf(v0.z - bm); v0.w = expf(v0.w - bm);
    v1.x = expf(v1.x - bm); v1.y = expf(v1.y - bm);
    v1.z = expf(v1.z - bm); v1.w = expf(v1.w - bm);

    float s = v0.x + v0.y + v0.z + v0.w + v1.x + v1.y + v1.z + v1.w;
    float ws = warp_sum(s);
    if ((tid & 31) == 0) red[tid >> 5] = ws;
    __syncthreads();
    float bs = 0.f;
#pragma unroll
    for (int i = 0; i < 8; i++) bs += red[i];

    const float inv = 1.f / bs;
    v0.x *= inv; v0.y *= inv; v0.z *= inv; v0.w *= inv;
    v1.x *= inv; v1.y *= inv; v1.z *= inv; v1.w *= inv;

    *reinterpret_cast<float4*>(p + tid * 4)        = v0;
    *reinterpret_cast<float4*>(p + 1024 + tid * 4) = v1;
}

// ---------------------------------------------------------------------------
// Launch
// ---------------------------------------------------------------------------
extern "C" void kernel_launch(void* const* d_in, const int* in_sizes, int n_in,
                              void* d_out, int out_size)
{
    const float* Xq   = (const float*)d_in[0];  // [B,Sq,H]
    const float* Xk   = (const float*)d_in[1];  // [B,Skv,H]
    const float* mask = (const float*)d_in[2];  // [B,Skv]
    const float* Wq   = (const float*)d_in[3];  // [H,H]
    const float* bq   = (const float*)d_in[4];
    const float* Wk   = (const float*)d_in[5];
    const float* bk   = (const float*)d_in[6];
    const float* Wv   = (const float*)d_in[7];
    const float* bv   = (const float*)d_in[8];
    float* out = (float*)d_out;                 // [B,Sq,H]

    float *Q, *K, *V, *S;
    cudaGetSymbolAddress((void**)&Q, g_Q);
    cudaGetSymbolAddress((void**)&K, g_K);
    cudaGetSymbolAddress((void**)&V, g_V);
    cudaGetSymbolAddress((void**)&S, g_S);

    const float scale = 1.f / 32.f;  // 1/sqrt(1024)

    // 1-3) Projections: [B*S, H] @ [H, H] + bias, NN
    {
        dim3 grid(HID / 128, (BATCH * SQ) / 128, 1);
        gemm_kern<false, 1><<<grid, 256>>>(Xq, Wq, bq, Q,
            BATCH * SQ, HID, HID, 0, 0, 0, 1.f);
        gemm_kern<false, 1><<<grid, 256>>>(Xk, Wk, bk, K,
            BATCH * SKV, HID, HID, 0, 0, 0, 1.f);
        gemm_kern<false, 1><<<grid, 256>>>(Xk, Wv, bv, V,
            BATCH * SKV, HID, HID, 0, 0, 0, 1.f);
    }

    // 4) Scores: S[b] = Q[b] @ K[b]^T * scale + (1-mask)*-1e4  (NT, batched)
    {
        dim3 grid(SKV / 128, SQ / 128, BATCH);
        gemm_kern<true, 2><<<grid, 256>>>(Q, K, mask, S,
            SQ, SKV, HID,
            (size_t)SQ * HID, (size_t)SKV * HID, (size_t)SQ * SKV, scale);
    }

    // 5) Row softmax in place
    softmax_kern<<<BATCH * SQ, 256>>>(S);

    // 6) Output: out[b] = S[b] @ V[b]  (NN, batched)
    {
        dim3 grid(HID / 128, SQ / 128, BATCH);
        gemm_kern<false, 0><<<grid, 256>>>(S, V, nullptr, out,
            SQ, HID, SKV,
            (size_t)SQ * SKV, (size_t)SKV * HID, (size_t)SQ * HID, 1.f);
    }
}